// round 7
// baseline (speedup 1.0000x reference)
#include <cuda_runtime.h>
#include <cstdint>

// Problem constants
#define NB   64
#define NT   2048
#define EMBD 32
#define HID  256
#define KTOT (EMBD + HID)     // 288
#define CSIZE  8              // cluster size = unit slices
#define BSLICE 16             // batch slices (one cluster each)
#define NCTA  (CSIZE * BSLICE)   // 128
#define UPC   32              // units per CTA
#define NROWS (4 * UPC)       // 128 gate rows per CTA
#define BPC   (NB / BSLICE)   // 4 batches per CTA
#define NTHREADS 256

#define WPAD  292             // W row stride (floats): 16B-aligned
#define XEPAD 36              // xe row stride (floats): 144B, 16B-aligned

__device__ __forceinline__ float sigf(float x)  { return 1.0f / (1.0f + __expf(-x)); }
__device__ __forceinline__ float tanha(float x) { return 2.0f / (1.0f + __expf(-2.0f * x)) - 1.0f; }

#define LDS2U64(a, b, addr) \
    asm volatile("ld.shared.v2.u64 {%0,%1}, [%2];" : "=l"(a), "=l"(b) : "r"(addr))
#define FMA2(acc, w, z) \
    asm volatile("fma.rn.f32x2 %0, %1, %2, %0;" : "+l"(acc) : "l"(w), "l"(z))
#define CLUSTER_SYNC() do { \
    asm volatile("barrier.cluster.arrive.aligned;" ::: "memory"); \
    asm volatile("barrier.cluster.wait.aligned;" ::: "memory"); \
} while (0)

__global__ void __launch_bounds__(NTHREADS, 1) __cluster_dims__(CSIZE, 1, 1)
lstm_cluster_kernel(const int* __restrict__ x,        // [NB, NT]
                    const int* __restrict__ lengths,  // [NB]
                    const float* __restrict__ emb,    // [VOCAB, EMBD]
                    const float* __restrict__ W_ih,   // [4*HID, EMBD]
                    const float* __restrict__ W_hh,   // [4*HID, HID]
                    const float* __restrict__ b_ih,   // [4*HID]
                    const float* __restrict__ b_hh,   // [4*HID]
                    float* __restrict__ out)          // [NB, 1, HID]
{
    extern __shared__ float sm[];
    float* w_s  = sm;                        // [NROWS][WPAD]      (149504 B)
    float* xe_s = w_s + NROWS * WPAD;        // [BPC][XEPAD]
    float* hb   = xe_s + BPC * XEPAD;        // [2][BPC][HID]      (8192 B)
    float* gs   = hb + 2 * BPC * HID;        // [NROWS][BPC]
    float* bs   = gs + NROWS * BPC;          // [NROWS]
    int* lenS   = (int*)(bs + NROWS);        // [NB]
    int* mlS    = lenS + NB;

    const int tid = threadIdx.x;
    const int cta = blockIdx.x;
    const int us  = cta & (CSIZE - 1);       // cluster rank (unit slice)
    const int bsl = cta >> 3;                // batch slice (cluster id)
    const int u0  = us * UPC;
    const int bb0 = bsl * BPC;

    // ---- one-time staging ----
    for (int idx = tid; idx < NROWS * KTOT; idx += NTHREADS) {
        int r = idx / KTOT;
        int k = idx - r * KTOT;
        int g = r >> 5, du = r & 31;
        int grow = g * HID + u0 + du;
        float v = (k < EMBD) ? W_ih[grow * EMBD + k]
                             : W_hh[grow * HID + (k - EMBD)];
        w_s[r * WPAD + k] = v;
    }
    if (tid < NROWS) {
        int g = tid >> 5, du = tid & 31;
        int grow = g * HID + u0 + du;
        bs[tid] = b_ih[grow] + b_hh[grow];
    }
    if (tid < NB) lenS[tid] = lengths[tid];
    __syncthreads();
    if (tid == 0) {
        int m = 1;
        for (int b = 0; b < NB; b++) m = max(m, lenS[b]);
        *mlS = m;
    }
    // gather xe(0)
    if (tid < BPC) {
        int tok = x[(bb0 + tid) * NT + 0];
        const float4* e = (const float4*)(emb + (long)tok * EMBD);
        float4* zr = (float4*)(xe_s + tid * XEPAD);
        #pragma unroll
        for (int q = 0; q < EMBD / 4; q++) zr[q] = e[q];
    }
    __syncthreads();
    const int maxlen = *mlS;

    // rendezvous: all cluster CTAs alive before any DSMEM traffic
    CLUSTER_SYNC();

    // shared base address (32-bit) for asm addressing
    uint32_t sb;
    asm("{ .reg .u64 t; cvta.to.shared.u64 t, %1; cvt.u32.u64 %0, t; }"
        : "=r"(sb) : "l"(sm));
    const uint32_t XEO = (uint32_t)(NROWS * WPAD) * 4u;
    const uint32_t HBO = XEO + (uint32_t)(BPC * XEPAD) * 4u;

    // mapa'd peer hb base addresses (loop-invariant)
    uint32_t peer_hb[CSIZE];
    #pragma unroll
    for (int r = 0; r < CSIZE; r++) {
        asm("mapa.shared::cluster.u32 %0, %1, %2;"
            : "=r"(peer_hb[r]) : "r"(sb + HBO), "r"(r));
    }

    // GEMM mapping: 256 threads = 128 rows x 2 batch-slots; batches bp, bp+2
    const int row = tid >> 1;
    const int bp  = tid & 1;
    const uint32_t waddr0 = sb + (uint32_t)(row * WPAD) * 4u;
    const uint32_t waddrH = waddr0 + (uint32_t)EMBD * 4u;
    const uint32_t xeA = sb + XEO + (uint32_t)(bp * XEPAD) * 4u;
    const uint32_t xeB = xeA + (uint32_t)(2 * XEPAD) * 4u;
    const float bias = bs[row];
    float* goutA = gs + row * BPC + bp;
    float* goutB = goutA + 2;

    // phase-2 mapping (tid < 128): unit u_l = tid&31, batch b2 = tid>>5
    const int u_l = tid & 31;
    const int b2  = (tid >> 5) & 3;
    const int bg  = bb0 + b2;
    const int uu  = u0 + u_l;
    const int mylen = lenS[bg];
    float c_r = 0.0f, h_r = 0.0f;

    unsigned long long Aa, Ab;
    const unsigned long long bias_pk =
        (unsigned long long)__float_as_uint(bias);   // (bias, 0)

    // ---- prologue: acc = bias + W_ih . xe(0) ----
    Aa = bias_pk; Ab = bias_pk;
    #pragma unroll
    for (int k = 0; k < EMBD; k += 4) {
        unsigned long long W01, W23, Z01a, Z23a, Z01b, Z23b;
        LDS2U64(W01, W23, waddr0 + k * 4);
        LDS2U64(Z01a, Z23a, xeA + k * 4);
        LDS2U64(Z01b, Z23b, xeB + k * 4);
        FMA2(Aa, W01, Z01a); FMA2(Ab, W01, Z01b);
        FMA2(Aa, W23, Z23a); FMA2(Ab, W23, Z23b);
    }

    for (int t = 0; t < maxlen; t++) {
        // ---- acc += W_hh . h(t-1) from local SMEM hb[t&1] ----
        if (t > 0) {
            const uint32_t hA = sb + HBO + (uint32_t)((((t & 1) * BPC) + bp) * HID) * 4u;
            const uint32_t hB = hA + (uint32_t)(2 * HID) * 4u;
            #pragma unroll 4
            for (int k = 0; k < HID; k += 4) {
                unsigned long long W01, W23, Z01a, Z23a, Z01b, Z23b;
                LDS2U64(W01, W23, waddrH + k * 4);
                LDS2U64(Z01a, Z23a, hA + k * 4);
                LDS2U64(Z01b, Z23b, hB + k * 4);
                FMA2(Aa, W01, Z01a); FMA2(Ab, W01, Z01b);
                FMA2(Aa, W23, Z23a); FMA2(Ab, W23, Z23b);
            }
        }
        {
            float a_lo = __uint_as_float((uint32_t)Aa);
            float a_hi = __uint_as_float((uint32_t)(Aa >> 32));
            float b_lo = __uint_as_float((uint32_t)Ab);
            float b_hi = __uint_as_float((uint32_t)(Ab >> 32));
            *goutA = a_lo + a_hi;
            *goutB = b_lo + b_hi;
        }
        __syncthreads();

        // ---- phase 2 (tid < 128): activations, state update, DSMEM push ----
        if (tid < 128) {
            float gi = gs[(0 * UPC + u_l) * BPC + b2];
            float gf = gs[(1 * UPC + u_l) * BPC + b2];
            float gg = gs[(2 * UPC + u_l) * BPC + b2];
            float go = gs[(3 * UPC + u_l) * BPC + b2];
            float iv = sigf(gi), fv = sigf(gf), gv = tanha(gg), ov = sigf(go);
            float cn = fmaf(fv, c_r, iv * gv);
            float hn = ov * tanha(cn);
            if (t < mylen) { c_r = cn; h_r = hn; }
            // push h(t) into every cluster CTA's hb[(t+1)&1] —
            // ONLY if someone will read it (t+1 exists). Keeping the last
            // iteration store-free makes exit race-free.
            if (t + 1 < maxlen) {
                uint32_t off = (uint32_t)(((((t + 1) & 1) * BPC + b2) * HID) + u0 + u_l) * 4u;
                #pragma unroll
                for (int r = 0; r < CSIZE; r++) {
                    asm volatile("st.shared::cluster.f32 [%0], %1;"
                                 :: "r"(peer_hb[r] + off), "f"(h_r));
                }
            }
        }

        if (t + 1 < maxlen) {
            // split cluster barrier: arrive (releases my DSMEM stores) ...
            asm volatile("barrier.cluster.arrive.aligned;" ::: "memory");
            // ... overlap: gather xe(t+1)
            if (tid < BPC) {
                int tok = x[(bb0 + tid) * NT + (t + 1)];
                const float4* e = (const float4*)(emb + (long)tok * EMBD);
                float4* zr = (float4*)(xe_s + tid * XEPAD);
                #pragma unroll
                for (int q = 0; q < EMBD / 4; q++) zr[q] = e[q];
            }
            __syncthreads();
            // ... overlap: input-projection GEMM for t+1
            Aa = bias_pk; Ab = bias_pk;
            #pragma unroll
            for (int k = 0; k < EMBD; k += 4) {
                unsigned long long W01, W23, Z01a, Z23a, Z01b, Z23b;
                LDS2U64(W01, W23, waddr0 + k * 4);
                LDS2U64(Z01a, Z23a, xeA + k * 4);
                LDS2U64(Z01b, Z23b, xeB + k * 4);
                FMA2(Aa, W01, Z01a); FMA2(Ab, W01, Z01b);
                FMA2(Aa, W23, Z23a); FMA2(Ab, W23, Z23b);
            }
            // wait: all peers' h(t) pushes visible in my hb
            asm volatile("barrier.cluster.wait.aligned;" ::: "memory");
        }
    }

    // final frozen h == reference out[:, -1, :]
    if (tid < 128) out[bg * HID + uu] = h_r;

    // defensive: no CTA leaves while any cluster peer could still be active
    CLUSTER_SYNC();
}

extern "C" void kernel_launch(void* const* d_in, const int* in_sizes, int n_in,
                              void* d_out, int out_size) {
    const int*   x       = (const int*)d_in[0];
    const int*   lengths = (const int*)d_in[1];
    const float* emb     = (const float*)d_in[2];
    const float* W_ih    = (const float*)d_in[3];
    const float* W_hh    = (const float*)d_in[4];
    const float* b_ih    = (const float*)d_in[5];
    const float* b_hh    = (const float*)d_in[6];
    float* out = (float*)d_out;

    const int smem_bytes =
        (NROWS * WPAD + BPC * XEPAD + 2 * BPC * HID + NROWS * BPC + NROWS) * (int)sizeof(float)
        + (NB + 1) * (int)sizeof(int) + 32;

    cudaFuncSetAttribute(lstm_cluster_kernel,
                         cudaFuncAttributeMaxDynamicSharedMemorySize, smem_bytes);

    lstm_cluster_kernel<<<NCTA, NTHREADS, smem_bytes>>>(
        x, lengths, emb, W_ih, W_hh, b_ih, b_hh, out);
}

// round 8
// speedup vs baseline: 1.4005x; 1.4005x over previous
#include <cuda_runtime.h>
#include <cstdint>

// Problem constants
#define NB   64
#define NT   2048
#define EMBD 32
#define HID  256
#define KTOT (EMBD + HID)     // 288
#define USLICE 16             // unit slices (producers per bsl group)
#define BSLICE 8              // batch slices
#define NCTA  (USLICE * BSLICE)   // 128
#define UPC   16              // units per CTA
#define NROWS (4 * UPC)       // 64 gate rows per CTA
#define BPC   (NB / BSLICE)   // 8 batches per CTA
#define NTHREADS 256
#define NCHUNK 4              // h consumed in 4 chunks of 64 k (4 producers each)
#define PPCH  (USLICE / NCHUNK)   // producers per chunk = 4

#define WPAD 292              // floats; %32==4 -> 8 rows/warp on banks 0/4/../28; 16B-aligned
#define ZPAD 296              // floats; %32==8 -> 4 bp rows on banks 0/8/16/24; 16B-aligned

// Persistent cross-CTA state
__device__ float g_H[2][BSLICE][BPC][HID];   // [buf][bsl][batch][unit]
__device__ int   g_flag[BSLICE][USLICE];     // steps completed by producer (us,bsl)

__global__ void lstm_init_kernel() {
    int i = threadIdx.x;
    if (i < BSLICE * USLICE) ((int*)g_flag)[i] = 0;
}

__device__ __forceinline__ float sigf(float x)  { return 1.0f / (1.0f + __expf(-x)); }
__device__ __forceinline__ float tanha(float x) { return 2.0f / (1.0f + __expf(-2.0f * x)) - 1.0f; }

__device__ __forceinline__ int ld_acq(const int* p) {
    int v;
    asm volatile("ld.acquire.gpu.b32 %0, [%1];" : "=r"(v) : "l"(p));
    return v;
}

#define LDS2U64(a, b, addr) \
    asm volatile("ld.shared.v2.u64 {%0,%1}, [%2];" : "=l"(a), "=l"(b) : "r"(addr))
#define FMA2(acc, w, z) \
    asm volatile("fma.rn.f32x2 %0, %1, %2, %0;" : "+l"(acc) : "l"(w), "l"(z))

__global__ void __launch_bounds__(NTHREADS, 1)
lstm_persist_kernel(const int* __restrict__ x,        // [NB, NT]
                    const int* __restrict__ lengths,  // [NB]
                    const float* __restrict__ emb,    // [VOCAB, EMBD]
                    const float* __restrict__ W_ih,   // [4*HID, EMBD]
                    const float* __restrict__ W_hh,   // [4*HID, HID]
                    const float* __restrict__ b_ih,   // [4*HID]
                    const float* __restrict__ b_hh,   // [4*HID]
                    float* __restrict__ out)          // [NB, 1, HID]
{
    extern __shared__ float sm[];
    float* w_s  = sm;                        // [NROWS][WPAD]   (74752 B)
    float* z_s  = w_s + NROWS * WPAD;        // [BPC][ZPAD]     (9472 B)   k: 0..31 xe, 32..287 h
    float* gs   = z_s + BPC * ZPAD;          // [NROWS][BPC]    (2048 B)
    float* bs   = gs + NROWS * BPC;          // [NROWS]
    int* lenS   = (int*)(bs + NROWS);        // [NB]
    int* mlS    = lenS + NB;

    const int tid = threadIdx.x;
    const int cta = blockIdx.x;
    const int us  = cta & (USLICE - 1);      // unit slice 0..15
    const int bsl = cta >> 4;                // batch slice 0..7
    const int u0  = us * UPC;
    const int bb0 = bsl * BPC;

    // ---- one-time staging: W rows (4 gates x 16 units), biases, lengths ----
    for (int idx = tid; idx < NROWS * KTOT; idx += NTHREADS) {
        int r = idx / KTOT;
        int k = idx - r * KTOT;
        int g = r >> 4, du = r & 15;
        int grow = g * HID + u0 + du;
        float v = (k < EMBD) ? W_ih[grow * EMBD + k]
                             : W_hh[grow * HID + (k - EMBD)];
        w_s[r * WPAD + k] = v;
    }
    if (tid < NROWS) {
        int g = tid >> 4, du = tid & 15;
        int grow = g * HID + u0 + du;
        bs[tid] = b_ih[grow] + b_hh[grow];
    }
    if (tid < NB) lenS[tid] = lengths[tid];
    __syncthreads();
    if (tid == 0) {
        int m = 1;
        for (int b = 0; b < NB; b++) m = max(m, lenS[b]);
        *mlS = m;
    }
    // zero h region of z (t=0 reads zeros)
    for (int i = tid; i < BPC * HID; i += NTHREADS) {
        int b = i >> 8, u = i & 255;
        z_s[b * ZPAD + EMBD + u] = 0.0f;
    }
    // gather xe(0)
    if (tid < BPC) {
        int tok = x[(bb0 + tid) * NT + 0];
        const float4* e = (const float4*)(emb + (long)tok * EMBD);
        float4* zr = (float4*)(z_s + tid * ZPAD);
        #pragma unroll
        for (int q = 0; q < EMBD / 4; q++) zr[q] = e[q];
    }
    __syncthreads();
    const int maxlen = *mlS;

    // shared base for asm addressing
    uint32_t sb;
    asm("{ .reg .u64 t; cvta.to.shared.u64 t, %1; cvt.u32.u64 %0, t; }"
        : "=r"(sb) : "l"(sm));
    const uint32_t ZOFF = (uint32_t)(NROWS * WPAD) * 4u;

    // GEMM mapping: 256 threads = 64 rows x 4 batch-slots; batches bp, bp+4
    const int row = tid >> 2;                // 0..63
    const int bp  = tid & 3;                 // 0..3
    const uint32_t waddr0 = sb + (uint32_t)(row * WPAD) * 4u;
    const uint32_t zaddrA = sb + ZOFF + (uint32_t)(bp * ZPAD) * 4u;
    const uint32_t zaddrB = zaddrA + (uint32_t)(4 * ZPAD) * 4u;
    const float bias = bs[row];
    float* goutA = gs + row * BPC + bp;
    float* goutB = goutA + 4;

    // phase-2 mapping (tid < 128): unit u_l = tid>>3, batch b2 = tid&7
    const int u_l = tid >> 3;
    const int b2  = tid & 7;
    const int bg  = bb0 + b2;
    const int uu  = u0 + (u_l & 15);
    const int mylen = lenS[bg];
    float c_r = 0.0f, h_r = 0.0f;

    // staging mapping (tid < 128): one float4 of one chunk
    const int sb_b  = tid >> 4;              // batch 0..7
    const int sb_u4 = (tid & 15) * 4;        // unit offset within 64-unit chunk

    unsigned long long Aa, Ab;
    const unsigned long long bias_pk =
        (unsigned long long)__float_as_uint(bias);   // (bias, 0)

    // ---- prologue: acc = bias + W_ih . xe(0) ----
    Aa = bias_pk; Ab = bias_pk;
    #pragma unroll
    for (int k = 0; k < EMBD; k += 4) {
        unsigned long long W01, W23, Z01a, Z23a, Z01b, Z23b;
        LDS2U64(W01, W23, waddr0 + k * 4);
        LDS2U64(Z01a, Z23a, zaddrA + k * 4);
        LDS2U64(Z01b, Z23b, zaddrB + k * 4);
        FMA2(Aa, W01, Z01a); FMA2(Ab, W01, Z01b);
        FMA2(Aa, W23, Z23a); FMA2(Ab, W23, Z23b);
    }

    float4 preg = make_float4(0.f, 0.f, 0.f, 0.f);   // prefetched h chunk fragment

    for (int t = 0; t < maxlen; t++) {
        // ---- chunked h GEMM: k = 32..287 in 4 chunks of 64 ----
        #pragma unroll
        for (int c = 0; c < NCHUNK; c++) {
            // STS the prefetched fragment of chunk c (loaded under cover of prior work)
            if (t > 0 && tid < 128) {
                *(float4*)(z_s + sb_b * ZPAD + EMBD + c * 64 + sb_u4) = preg;
            }
            // poll flags for chunk c+1's producers (before the bar)
            if (t > 0 && c < NCHUNK - 1 && tid < PPCH) {
                const int* f = &g_flag[bsl][(c + 1) * PPCH + tid];
                while (ld_acq(f) < t) { __nanosleep(32); }
            }
            __syncthreads();
            // prefetch chunk c+1 (hidden by chunk c compute)
            if (t > 0 && c < NCHUNK - 1 && tid < 128) {
                const float* src = &g_H[t & 1][bsl][sb_b][(c + 1) * 64 + sb_u4];
                asm volatile("ld.global.cg.v4.f32 {%0,%1,%2,%3}, [%4];"
                             : "=f"(preg.x), "=f"(preg.y), "=f"(preg.z), "=f"(preg.w)
                             : "l"(src));
            }
            // compute chunk c
            {
                const uint32_t wk  = waddr0 + (uint32_t)(EMBD + c * 64) * 4u;
                const uint32_t zkA = zaddrA + (uint32_t)(EMBD + c * 64) * 4u;
                const uint32_t zkB = zaddrB + (uint32_t)(EMBD + c * 64) * 4u;
                #pragma unroll 4
                for (int k = 0; k < 64; k += 4) {
                    unsigned long long W01, W23, Z01a, Z23a, Z01b, Z23b;
                    LDS2U64(W01, W23, wk + k * 4);
                    LDS2U64(Z01a, Z23a, zkA + k * 4);
                    LDS2U64(Z01b, Z23b, zkB + k * 4);
                    FMA2(Aa, W01, Z01a); FMA2(Ab, W01, Z01b);
                    FMA2(Aa, W23, Z23a); FMA2(Ab, W23, Z23b);
                }
            }
        }
        // gate = lo + hi of each k-split accumulator
        {
            float a_lo = __uint_as_float((uint32_t)Aa);
            float a_hi = __uint_as_float((uint32_t)(Aa >> 32));
            float b_lo = __uint_as_float((uint32_t)Ab);
            float b_hi = __uint_as_float((uint32_t)(Ab >> 32));
            *goutA = a_lo + a_hi;
            *goutB = b_lo + b_hi;
        }
        __syncthreads();

        // ---- phase 2: activations + state update (tid < 128) ----
        if (tid < 128) {
            float gi = gs[(0 * UPC + u_l) * BPC + b2];
            float gf = gs[(1 * UPC + u_l) * BPC + b2];
            float gg = gs[(2 * UPC + u_l) * BPC + b2];
            float go = gs[(3 * UPC + u_l) * BPC + b2];
            float iv = sigf(gi), fv = sigf(gf), gv = tanha(gg), ov = sigf(go);
            float cn = fmaf(fv, c_r, iv * gv);
            float hn = ov * tanha(cn);
            if (t < mylen) { c_r = cn; h_r = hn; }
            g_H[(t + 1) & 1][bsl][b2][uu] = h_r;     // h(t) -> buffer read at step t+1
        }
        __syncthreads();   // all h stores issued CTA-wide

        // ---- publish BEFORE any polling (no circular wait) ----
        if (tid == 0) {
            __threadfence();                 // release h stores to gpu scope
            g_flag[bsl][us] = t + 1;
        }

        if (t + 1 < maxlen) {
            // overlap window: xe(t+1) gather + chunk0 flag poll + input GEMM
            if (tid < BPC) {
                int tok = x[(bb0 + tid) * NT + (t + 1)];
                const float4* e = (const float4*)(emb + (long)tok * EMBD);
                float4* zr = (float4*)(z_s + tid * ZPAD);
                #pragma unroll
                for (int q = 0; q < EMBD / 4; q++) zr[q] = e[q];
            }
            if (tid < PPCH) {
                const int* f = &g_flag[bsl][tid];    // chunk 0 producers
                while (ld_acq(f) < t + 1) { __nanosleep(32); }
            }
            __syncthreads();
            // prefetch chunk 0 of h(t) (hidden by input GEMM below)
            if (tid < 128) {
                const float* src = &g_H[(t + 1) & 1][bsl][sb_b][sb_u4];
                asm volatile("ld.global.cg.v4.f32 {%0,%1,%2,%3}, [%4];"
                             : "=f"(preg.x), "=f"(preg.y), "=f"(preg.z), "=f"(preg.w)
                             : "l"(src));
            }
            // input-projection GEMM for t+1
            Aa = bias_pk; Ab = bias_pk;
            #pragma unroll
            for (int k = 0; k < EMBD; k += 4) {
                unsigned long long W01, W23, Z01a, Z23a, Z01b, Z23b;
                LDS2U64(W01, W23, waddr0 + k * 4);
                LDS2U64(Z01a, Z23a, zaddrA + k * 4);
                LDS2U64(Z01b, Z23b, zaddrB + k * 4);
                FMA2(Aa, W01, Z01a); FMA2(Ab, W01, Z01b);
                FMA2(Aa, W23, Z23a); FMA2(Ab, W23, Z23b);
            }
        }
    }

    // final frozen h == reference out[:, -1, :]
    if (tid < 128) out[bg * HID + uu] = h_r;
}

extern "C" void kernel_launch(void* const* d_in, const int* in_sizes, int n_in,
                              void* d_out, int out_size) {
    const int*   x       = (const int*)d_in[0];
    const int*   lengths = (const int*)d_in[1];
    const float* emb     = (const float*)d_in[2];
    const float* W_ih    = (const float*)d_in[3];
    const float* W_hh    = (const float*)d_in[4];
    const float* b_ih    = (const float*)d_in[5];
    const float* b_hh    = (const float*)d_in[6];
    float* out = (float*)d_out;

    const int smem_bytes =
        (NROWS * WPAD + BPC * ZPAD + NROWS * BPC + NROWS) * (int)sizeof(float)
        + (NB + 1) * (int)sizeof(int) + 32;

    cudaFuncSetAttribute(lstm_persist_kernel,
                         cudaFuncAttributeMaxDynamicSharedMemorySize, smem_bytes);

    lstm_init_kernel<<<1, 128>>>();
    lstm_persist_kernel<<<NCTA, NTHREADS, smem_bytes>>>(
        x, lengths, emb, W_ih, W_hh, b_ih, b_hh, out);
}